// round 11
// baseline (speedup 1.0000x reference)
#include <cuda_runtime.h>
#include <cuda_bf16.h>
#include <stdint.h>

#define N_NODES 50000
#define E_EDGES 800000
#define IN_C    10
#define HID     96
#define OUT_C   48
#define SCAN_B  196          // ceil(50000/256)
#define FLAGB   (1 << 30)

// ---- scratch (device globals; zero-init at module load) ----
__device__ int    g_cnt[N_NODES];
__device__ int    g_pub[256];               // decoupled-lookback (flag|agg)
__device__ int    g_off[N_NODES + 1];
__device__ int    g_cur[N_NODES];
__device__ float  g_dis[N_NODES];
__device__ int    g_src[E_EDGES];           // CSR src indices
__device__ float4 g_xs4[N_NODES * 3];       // x*dis, padded 10->12 floats
__device__ float  g_hs [N_NODES * HID];     // relu(h) * dis

// count: 2 edges per thread (cnt zeroed by k_fill of the previous call;
// device globals are zero-initialized, so the first call is also correct)
__global__ void k_count(const int* __restrict__ ei) {
    int t = blockIdx.x * blockDim.x + threadIdx.x;
    if (t * 2 >= E_EDGES) return;
    int2 c2 = __ldg((const int2*)(ei + E_EDGES) + t);
    atomicAdd(&g_cnt[c2.x], 1);
    atomicAdd(&g_cnt[c2.y], 1);
}

// Single-pass scan (decoupled lookback) + dis + cursors + padded xs4.
__global__ void k_scanfuse(const float* __restrict__ x) {
    __shared__ int ws[8];
    __shared__ int s_prefix;
    int b = blockIdx.x, t = threadIdx.x;
    int idx = b * 256 + t;
    int v = (idx < N_NODES) ? g_cnt[idx] : 0;
    int inc = v;
    #pragma unroll
    for (int o = 1; o < 32; o <<= 1) {
        int u = __shfl_up_sync(0xffffffffu, inc, o);
        if ((t & 31) >= o) inc += u;
    }
    if ((t & 31) == 31) ws[t >> 5] = inc;
    __syncthreads();
    if (t < 8) {
        int wv = ws[t];
        int winc = wv;
        #pragma unroll
        for (int o = 1; o < 8; o <<= 1) {
            int u = __shfl_up_sync(0xffu, winc, o);
            if (t >= o) winc += u;
        }
        ws[t] = winc - wv;
        if (t == 7)
            *((volatile int*)&g_pub[b]) = winc | FLAGB;
    }
    __syncwarp(0xffffffffu);
    if (t < 32) {
        int sum = 0;
        for (int p = t; p < b; p += 32) {
            int pv;
            do { pv = *((volatile int*)&g_pub[p]); } while (!(pv & FLAGB));
            sum += pv & ~FLAGB;
        }
        #pragma unroll
        for (int o = 16; o > 0; o >>= 1)
            sum += __shfl_down_sync(0xffffffffu, sum, o);
        if (t == 0) s_prefix = sum;
    }
    __syncthreads();
    if (idx < N_NODES) {
        int off = s_prefix + ws[t >> 5] + (inc - v);
        g_off[idx] = off;
        g_cur[idx] = off;
        float d = rsqrtf((float)(v + 1));
        g_dis[idx] = d;
        const float* xr = x + (size_t)idx * IN_C;
        float vals[12];
        #pragma unroll
        for (int c = 0; c < IN_C; c++) vals[c] = __ldg(&xr[c]) * d;
        vals[10] = 0.0f; vals[11] = 0.0f;
        float4* xo = g_xs4 + (size_t)idx * 3;
        xo[0] = make_float4(vals[0], vals[1], vals[2], vals[3]);
        xo[1] = make_float4(vals[4], vals[5], vals[6], vals[7]);
        xo[2] = make_float4(vals[8], vals[9], vals[10], vals[11]);
    }
    if (idx == 0) g_off[N_NODES] = E_EDGES;
}

// CSR fill (src only) + reset cnt/pub for the next call
__global__ void k_fill(const int* __restrict__ ei) {
    int e = blockIdx.x * blockDim.x + threadIdx.x;
    if (e < 256) g_pub[e] = 0;
    if (e < N_NODES) g_cnt[e] = 0;
    if (e >= E_EDGES) return;
    int row = __ldg(&ei[e]);
    int col = __ldg(&ei[E_EDGES + e]);
    int pos = atomicAdd(&g_cur[col], 1);
    g_src[pos] = row;
}

// Fused layer 1: agg = dis[n]*(xs[n] + sum xs[src]); hs = relu(agg@W1+b1)*dis.
// block (96,4): gather = 32 groups x 3 float4 channels; W1/b1 via __ldg (L1).
__global__ void k_fused1(const float* __restrict__ W1,
                         const float* __restrict__ b1) {
    __shared__ float4 part[4][32][3];
    __shared__ float  sagg[4][12];
    int tx = threadIdx.x, ty = threadIdx.y;
    int n = blockIdx.x * 4 + ty;

    int g  = tx / 3;          // 0..31
    int c4 = tx - g * 3;      // 0..2
    float4 p = make_float4(0.f, 0.f, 0.f, 0.f);
    if (n < N_NODES) {
        int s = g_off[n], e = g_off[n + 1];
        for (int i = s + g; i < e; i += 32) {
            int src = __ldg(&g_src[i]);
            float4 v = __ldg(&g_xs4[(size_t)src * 3 + c4]);
            p.x += v.x; p.y += v.y; p.z += v.z; p.w += v.w;
        }
    }
    part[ty][g][c4] = p;
    __syncthreads();
    if (tx < 3 && n < N_NODES) {
        float4 a = __ldg(&g_xs4[(size_t)n * 3 + tx]);
        #pragma unroll 8
        for (int g2 = 0; g2 < 32; g2++) {
            float4 q = part[ty][g2][tx];
            a.x += q.x; a.y += q.y; a.z += q.z; a.w += q.w;
        }
        float d = g_dis[n];
        sagg[ty][tx * 4 + 0] = a.x * d;
        sagg[ty][tx * 4 + 1] = a.y * d;
        sagg[ty][tx * 4 + 2] = a.z * d;
        sagg[ty][tx * 4 + 3] = a.w * d;
    }
    __syncthreads();
    if (n >= N_NODES) return;
    float acc = __ldg(&b1[tx]);
    #pragma unroll
    for (int cc = 0; cc < IN_C; cc++)
        acc += sagg[ty][cc] * __ldg(&W1[cc * HID + tx]);
    g_hs[(size_t)n * HID + tx] = fmaxf(acc, 0.0f) * g_dis[n];
}

// Fused layer 2: aggregate 64 nodes (96-wide gather-sum) into shared,
// then the mu|logstd GEMM. Block = 384 threads, 64 nodes.
#define ONPB 64
__global__ __launch_bounds__(384) void k_aggout(
        const float* __restrict__ Wmu, const float* __restrict__ bmu,
        const float* __restrict__ Wls, const float* __restrict__ bls,
        float* __restrict__ out) {
    __shared__ __align__(16) float sW[24 * HID];      // 9216 B
    __shared__ float sh[ONPB * 97];                   // 24832 B
    __shared__ float sb[HID];
    int tid = threadIdx.x;
    int base = blockIdx.x * ONPB;

    // ---- phase A: aggregation; (96,4) mapping over 64 nodes ----
    {
        int j   = tid % 96;
        int ty2 = tid / 96;                           // 0..3
        for (int nd = ty2; nd < ONPB; nd += 4) {
            int n = base + nd;
            float acc = 0.0f;
            if (n < N_NODES) {
                acc = g_hs[(size_t)n * HID + j];
                int s = g_off[n], e = g_off[n + 1];
                int last = e - 1;
                for (int i = s; i < e; i += 8) {
                    #pragma unroll
                    for (int k = 0; k < 8; k++) {
                        int ik = min(i + k, last);
                        int sk = __ldg(&g_src[ik]);
                        float vv = __ldg(&g_hs[(size_t)sk * HID + j]);
                        acc += (i + k <= last) ? vv : 0.0f;
                    }
                }
                acc *= g_dis[n];
            }
            sh[nd * 97 + j] = acc;
        }
    }
    if (tid < HID)
        sb[tid] = (tid < OUT_C) ? __ldg(&bmu[tid]) : __ldg(&bls[tid - OUT_C]);
    __syncthreads();

    // ---- phase B: GEMM; (12,32) mapping: 8 j-cols x 2 nodes/thread ----
    int tx = tid % 12;
    int ty = tid / 12;                                // 0..31
    int j8 = tx * 8;
    float4 acc0[2], acc1[2];
    {
        float4 b0 = *(const float4*)&sb[j8];
        float4 b1v = *(const float4*)&sb[j8 + 4];
        #pragma unroll
        for (int k = 0; k < 2; k++) { acc0[k] = b0; acc1[k] = b1v; }
    }

    #pragma unroll
    for (int cb = 0; cb < 4; cb++) {
        for (int t = tid; t < 24 * 24; t += 384) {    // 576 float4
            int r = t / 24, q4 = (t - r * 24) * 4;
            int c = cb * 24 + r;
            float4 w;
            if (q4 < OUT_C) {
                w = __ldg((const float4*)&Wmu[c * OUT_C + q4]);
            } else {
                w = __ldg((const float4*)&Wls[c * OUT_C + (q4 - OUT_C)]);
            }
            *(float4*)&sW[r * HID + q4] = w;
        }
        __syncthreads();
        #pragma unroll 4
        for (int c = 0; c < 24; c++) {
            float4 w0 = *(const float4*)&sW[c * HID + j8];
            float4 w1 = *(const float4*)&sW[c * HID + j8 + 4];
            #pragma unroll
            for (int k = 0; k < 2; k++) {
                float a = sh[(ty * 2 + k) * 97 + cb * 24 + c];
                acc0[k].x += a * w0.x; acc0[k].y += a * w0.y;
                acc0[k].z += a * w0.z; acc0[k].w += a * w0.w;
                acc1[k].x += a * w1.x; acc1[k].y += a * w1.y;
                acc1[k].z += a * w1.z; acc1[k].w += a * w1.w;
            }
        }
        __syncthreads();
    }

    #pragma unroll
    for (int k = 0; k < 2; k++) {
        int n = base + ty * 2 + k;
        if (n >= N_NODES) continue;
        if (j8 < OUT_C) {
            *(float4*)&out[(size_t)n * OUT_C + j8] = acc0[k];
            *(float4*)&out[(size_t)n * OUT_C + j8 + 4] = acc1[k];
        } else {
            size_t o = (size_t)N_NODES * OUT_C + (size_t)n * OUT_C + (j8 - OUT_C);
            *(float4*)&out[o] = acc0[k];
            *(float4*)&out[o + 4] = acc1[k];
        }
    }
}

extern "C" void kernel_launch(void* const* d_in, const int* in_sizes, int n_in,
                              void* d_out, int out_size) {
    const float* x   = (const float*)d_in[0];
    const int*   ei  = (const int*)d_in[1];
    const float* W1  = (const float*)d_in[2];
    const float* b1  = (const float*)d_in[3];
    const float* Wmu = (const float*)d_in[4];
    const float* bmu = (const float*)d_in[5];
    const float* Wls = (const float*)d_in[6];
    const float* bls = (const float*)d_in[7];
    float* out = (float*)d_out;

    k_count<<<(E_EDGES / 2 + 255) / 256, 256>>>(ei);
    k_scanfuse<<<SCAN_B, 256>>>(x);
    k_fill<<<(E_EDGES + 255) / 256, 256>>>(ei);
    k_fused1<<<(N_NODES + 3) / 4, dim3(96, 4)>>>(W1, b1);
    k_aggout<<<(N_NODES + ONPB - 1) / ONPB, 384>>>(Wmu, bmu, Wls, bls, out);
}

// round 12
// speedup vs baseline: 1.2789x; 1.2789x over previous
#include <cuda_runtime.h>
#include <cuda_bf16.h>
#include <stdint.h>

#define N_NODES 50000
#define E_EDGES 800000
#define IN_C    10
#define HID     96
#define OUT_C   48
#define SCAN_B  196          // ceil(50000/256)
#define FLAGB   (1 << 30)

// ---- scratch (device globals; zero-init at module load) ----
__device__ int   g_cnt[N_NODES];
__device__ int   g_pub[256];                // decoupled-lookback (flag|agg)
__device__ int   g_off[N_NODES + 1];
__device__ int   g_cur[N_NODES];
__device__ float g_dis[N_NODES];
__device__ int   g_src[E_EDGES];            // CSR src indices
__device__ float g_xs [N_NODES * 12];       // x*dis, padded 10->12
__device__ float g_hs [N_NODES * HID];      // relu(h) * dis
__device__ float g_aggh[N_NODES * HID];

// count: 2 edges per thread (cnt zeroed by k_fill of the previous call;
// device globals are zero-initialized, so the first call is also correct)
__global__ void k_count(const int* __restrict__ ei) {
    int t = blockIdx.x * blockDim.x + threadIdx.x;
    if (t * 2 >= E_EDGES) return;
    int2 c2 = __ldg((const int2*)(ei + E_EDGES) + t);
    atomicAdd(&g_cnt[c2.x], 1);
    atomicAdd(&g_cnt[c2.y], 1);
}

// Single-pass scan (decoupled lookback) + dis + cursors + padded xs.
__global__ void k_scanfuse(const float* __restrict__ x) {
    __shared__ int ws[8];
    __shared__ int s_prefix;
    int b = blockIdx.x, t = threadIdx.x;
    int idx = b * 256 + t;
    int v = (idx < N_NODES) ? g_cnt[idx] : 0;
    int inc = v;
    #pragma unroll
    for (int o = 1; o < 32; o <<= 1) {
        int u = __shfl_up_sync(0xffffffffu, inc, o);
        if ((t & 31) >= o) inc += u;
    }
    if ((t & 31) == 31) ws[t >> 5] = inc;
    __syncthreads();
    if (t < 8) {
        int wv = ws[t];
        int winc = wv;
        #pragma unroll
        for (int o = 1; o < 8; o <<= 1) {
            int u = __shfl_up_sync(0xffu, winc, o);
            if (t >= o) winc += u;
        }
        ws[t] = winc - wv;
        if (t == 7)
            *((volatile int*)&g_pub[b]) = winc | FLAGB;
    }
    __syncwarp(0xffffffffu);
    if (t < 32) {
        int sum = 0;
        for (int p = t; p < b; p += 32) {
            int pv;
            do { pv = *((volatile int*)&g_pub[p]); } while (!(pv & FLAGB));
            sum += pv & ~FLAGB;
        }
        #pragma unroll
        for (int o = 16; o > 0; o >>= 1)
            sum += __shfl_down_sync(0xffffffffu, sum, o);
        if (t == 0) s_prefix = sum;
    }
    __syncthreads();
    if (idx < N_NODES) {
        int off = s_prefix + ws[t >> 5] + (inc - v);
        g_off[idx] = off;
        g_cur[idx] = off;
        float d = rsqrtf((float)(v + 1));
        g_dis[idx] = d;
        const float* xr = x + (size_t)idx * IN_C;
        float* xo = g_xs + (size_t)idx * 12;
        #pragma unroll
        for (int c = 0; c < IN_C; c++) xo[c] = __ldg(&xr[c]) * d;
        xo[10] = 0.0f; xo[11] = 0.0f;
    }
    if (idx == 0) g_off[N_NODES] = E_EDGES;
}

// CSR fill (src only) + reset cnt/pub for the next call
__global__ void k_fill(const int* __restrict__ ei) {
    int e = blockIdx.x * blockDim.x + threadIdx.x;
    if (e < 256) g_pub[e] = 0;
    if (e < N_NODES) g_cnt[e] = 0;
    if (e >= E_EDGES) return;
    int row = __ldg(&ei[e]);
    int col = __ldg(&ei[E_EDGES + e]);
    int pos = atomicAdd(&g_cur[col], 1);
    g_src[pos] = row;
}

// Fused layer 1, 64 nodes per 384-thread block (grid 782).
// Phase A: (12 ch x 32 node-slots) x 2 passes -> sagg[64][12] in shared.
// Phase B: register-tiled projection (8 j x 2 nodes / thread), relu*dis.
#define F1NPB 64
__global__ __launch_bounds__(384) void k_fused1(
        const float* __restrict__ W1, const float* __restrict__ b1) {
    __shared__ float sagg[F1NPB * 12];      // 3072 B
    __shared__ __align__(16) float sW1[IN_C * HID];   // 3840 B
    __shared__ float sb1[HID];
    int tid = threadIdx.x;
    int base = blockIdx.x * F1NPB;

    // stage W1/b1 (once per 64 nodes)
    for (int t = tid; t < IN_C * HID; t += 384) sW1[t] = __ldg(&W1[t]);
    if (tid < HID) sb1[tid] = __ldg(&b1[tid]);

    // ---- phase A: aggregation ----
    int c    = tid % 12;
    int half = tid / 12;                    // 0..31
    #pragma unroll
    for (int pass = 0; pass < 2; pass++) {
        int nd = pass * 32 + half;
        int n = base + nd;
        float acc = 0.0f;
        if (n < N_NODES) {
            acc = g_xs[(size_t)n * 12 + c];
            int s = g_off[n], e = g_off[n + 1];
            int last = e - 1;
            for (int i = s; i < e; i += 4) {
                #pragma unroll
                for (int k = 0; k < 4; k++) {
                    int ik = min(i + k, last);
                    int sk = __ldg(&g_src[ik]);
                    float vv = __ldg(&g_xs[(size_t)sk * 12 + c]);
                    acc += (i + k <= last) ? vv : 0.0f;
                }
            }
            acc *= g_dis[n];
        }
        sagg[nd * 12 + c] = acc;
    }
    __syncthreads();

    // ---- phase B: projection ----
    int tx = tid % 12, ty = tid / 12;       // tx: j-block, ty: node pair
    int j8 = tx * 8;
    float4 a0[2], a1[2];
    {
        float4 b0 = *(const float4*)&sb1[j8];
        float4 b1v = *(const float4*)&sb1[j8 + 4];
        #pragma unroll
        for (int k = 0; k < 2; k++) { a0[k] = b0; a1[k] = b1v; }
    }
    #pragma unroll
    for (int cc = 0; cc < IN_C; cc++) {
        float4 w0 = *(const float4*)&sW1[cc * HID + j8];
        float4 w1 = *(const float4*)&sW1[cc * HID + j8 + 4];
        #pragma unroll
        for (int k = 0; k < 2; k++) {
            float a = sagg[(ty * 2 + k) * 12 + cc];
            a0[k].x += a * w0.x; a0[k].y += a * w0.y;
            a0[k].z += a * w0.z; a0[k].w += a * w0.w;
            a1[k].x += a * w1.x; a1[k].y += a * w1.y;
            a1[k].z += a * w1.z; a1[k].w += a * w1.w;
        }
    }
    #pragma unroll
    for (int k = 0; k < 2; k++) {
        int n = base + ty * 2 + k;
        if (n >= N_NODES) continue;
        float d = g_dis[n];
        float4 r0, r1;
        r0.x = fmaxf(a0[k].x, 0.f) * d; r0.y = fmaxf(a0[k].y, 0.f) * d;
        r0.z = fmaxf(a0[k].z, 0.f) * d; r0.w = fmaxf(a0[k].w, 0.f) * d;
        r1.x = fmaxf(a1[k].x, 0.f) * d; r1.y = fmaxf(a1[k].y, 0.f) * d;
        r1.z = fmaxf(a1[k].z, 0.f) * d; r1.w = fmaxf(a1[k].w, 0.f) * d;
        *(float4*)&g_hs[(size_t)n * HID + j8] = r0;
        *(float4*)&g_hs[(size_t)n * HID + j8 + 4] = r1;
    }
}

// agg_h[n][j] = dis[n]*(hs[n][j] + sum hs[src][j]); branch-free 8-wide MLP
__global__ void k_aggh_csr() {
    int n = blockIdx.x * 4 + threadIdx.y;
    if (n >= N_NODES) return;
    int j = threadIdx.x;
    float acc = g_hs[(size_t)n * HID + j];
    int s = g_off[n], e = g_off[n + 1];
    int last = e - 1;
    for (int i = s; i < e; i += 8) {
        #pragma unroll
        for (int k = 0; k < 8; k++) {
            int ik = min(i + k, last);
            int sk = __ldg(&g_src[ik]);
            float vv = __ldg(&g_hs[(size_t)sk * HID + j]);
            acc += (i + k <= last) ? vv : 0.0f;
        }
    }
    g_aggh[(size_t)n * HID + j] = acc * g_dis[n];
}

// Output GEMM: block (12,8) = 96 thr; thread = 8 j-cols x 8 nodes; 64 nodes/blk.
#define ONPB 64
__global__ void k_out(const float* __restrict__ Wmu,
                      const float* __restrict__ bmu,
                      const float* __restrict__ Wls,
                      const float* __restrict__ bls,
                      float* __restrict__ out) {
    __shared__ __align__(16) float sW[24 * HID];
    __shared__ float sh[ONPB * 97];
    __shared__ float sb[HID];
    int tx = threadIdx.x, ty = threadIdx.y;
    int tid = ty * 12 + tx;
    int base = blockIdx.x * ONPB;

    if (tid < HID)
        sb[tid] = (tid < OUT_C) ? __ldg(&bmu[tid]) : __ldg(&bls[tid - OUT_C]);
    for (int t = tid; t < ONPB * 24; t += 96) {
        int nd = t / 24, c4 = (t - nd * 24) * 4;
        int n = base + nd;
        float4 v = (n < N_NODES) ? __ldg((const float4*)&g_aggh[(size_t)n * HID + c4])
                                 : make_float4(0.f, 0.f, 0.f, 0.f);
        float* dst = &sh[nd * 97 + c4];
        dst[0] = v.x; dst[1] = v.y; dst[2] = v.z; dst[3] = v.w;
    }

    int j8 = tx * 8;
    float4 acc0[8], acc1[8];
    {
        __syncthreads();
        float4 b0 = *(const float4*)&sb[j8];
        float4 b1v = *(const float4*)&sb[j8 + 4];
        #pragma unroll
        for (int k = 0; k < 8; k++) { acc0[k] = b0; acc1[k] = b1v; }
    }

    #pragma unroll
    for (int cb = 0; cb < 4; cb++) {
        for (int t = tid; t < 24 * 24; t += 96) {
            int r = t / 24, q4 = (t - r * 24) * 4;
            int c = cb * 24 + r;
            float4 w;
            if (q4 < OUT_C) {
                w = __ldg((const float4*)&Wmu[c * OUT_C + q4]);
            } else {
                w = __ldg((const float4*)&Wls[c * OUT_C + (q4 - OUT_C)]);
            }
            *(float4*)&sW[r * HID + q4] = w;
        }
        __syncthreads();
        #pragma unroll 4
        for (int c = 0; c < 24; c++) {
            float4 w0 = *(const float4*)&sW[c * HID + j8];
            float4 w1 = *(const float4*)&sW[c * HID + j8 + 4];
            #pragma unroll
            for (int k = 0; k < 8; k++) {
                float a = sh[(ty * 8 + k) * 97 + cb * 24 + c];
                acc0[k].x += a * w0.x; acc0[k].y += a * w0.y;
                acc0[k].z += a * w0.z; acc0[k].w += a * w0.w;
                acc1[k].x += a * w1.x; acc1[k].y += a * w1.y;
                acc1[k].z += a * w1.z; acc1[k].w += a * w1.w;
            }
        }
        __syncthreads();
    }

    #pragma unroll
    for (int k = 0; k < 8; k++) {
        int n = base + ty * 8 + k;
        if (n >= N_NODES) continue;
        if (j8 < OUT_C) {
            *(float4*)&out[(size_t)n * OUT_C + j8] = acc0[k];
            *(float4*)&out[(size_t)n * OUT_C + j8 + 4] = acc1[k];
        } else {
            size_t o = (size_t)N_NODES * OUT_C + (size_t)n * OUT_C + (j8 - OUT_C);
            *(float4*)&out[o] = acc0[k];
            *(float4*)&out[o + 4] = acc1[k];
        }
    }
}

extern "C" void kernel_launch(void* const* d_in, const int* in_sizes, int n_in,
                              void* d_out, int out_size) {
    const float* x   = (const float*)d_in[0];
    const int*   ei  = (const int*)d_in[1];
    const float* W1  = (const float*)d_in[2];
    const float* b1  = (const float*)d_in[3];
    const float* Wmu = (const float*)d_in[4];
    const float* bmu = (const float*)d_in[5];
    const float* Wls = (const float*)d_in[6];
    const float* bls = (const float*)d_in[7];
    float* out = (float*)d_out;

    k_count<<<(E_EDGES / 2 + 255) / 256, 256>>>(ei);
    k_scanfuse<<<SCAN_B, 256>>>(x);
    k_fill<<<(E_EDGES + 255) / 256, 256>>>(ei);
    k_fused1<<<(N_NODES + F1NPB - 1) / F1NPB, 384>>>(W1, b1);
    k_aggh_csr<<<(N_NODES + 3) / 4, dim3(HID, 4)>>>();
    k_out<<<(N_NODES + ONPB - 1) / ONPB, dim3(12, 8)>>>(Wmu, bmu, Wls, bls, out);
}

// round 14
// speedup vs baseline: 1.5871x; 1.2410x over previous
#include <cuda_runtime.h>
#include <cuda_bf16.h>
#include <stdint.h>

#define N_NODES 50000
#define E_EDGES 800000
#define IN_C    10
#define HID     96
#define OUT_C   48
#define SCAN_B  196          // ceil(50000/256)
#define FLAGB   (1 << 30)

// ---- scratch (device globals; zero-init at module load) ----
__device__ int   g_cnt[N_NODES];
__device__ int   g_pub[256];                // decoupled-lookback (flag|agg)
__device__ int   g_off[N_NODES + 1];
__device__ int   g_cur[N_NODES];
__device__ float g_dis[N_NODES];
__device__ int   g_src[E_EDGES];            // CSR src indices
__device__ float g_xs [N_NODES * 12];       // x*dis, padded 10->12
__device__ __align__(16) float g_hs  [N_NODES * HID];   // relu(h) * dis
__device__ __align__(16) float g_aggh[N_NODES * HID];

// count: 2 edges per thread (cnt zeroed by k_fill of the previous call;
// device globals are zero-initialized, so the first call is also correct)
__global__ void k_count(const int* __restrict__ ei) {
    int t = blockIdx.x * blockDim.x + threadIdx.x;
    if (t * 2 >= E_EDGES) return;
    int2 c2 = __ldg((const int2*)(ei + E_EDGES) + t);
    atomicAdd(&g_cnt[c2.x], 1);
    atomicAdd(&g_cnt[c2.y], 1);
}

// Single-pass scan (decoupled lookback) + dis + cursors + padded xs.
__global__ void k_scanfuse(const float* __restrict__ x) {
    __shared__ int ws[8];
    __shared__ int s_prefix;
    int b = blockIdx.x, t = threadIdx.x;
    int idx = b * 256 + t;
    int v = (idx < N_NODES) ? g_cnt[idx] : 0;
    int inc = v;
    #pragma unroll
    for (int o = 1; o < 32; o <<= 1) {
        int u = __shfl_up_sync(0xffffffffu, inc, o);
        if ((t & 31) >= o) inc += u;
    }
    if ((t & 31) == 31) ws[t >> 5] = inc;
    __syncthreads();
    if (t < 8) {
        int wv = ws[t];
        int winc = wv;
        #pragma unroll
        for (int o = 1; o < 8; o <<= 1) {
            int u = __shfl_up_sync(0xffu, winc, o);
            if (t >= o) winc += u;
        }
        ws[t] = winc - wv;
        if (t == 7)
            *((volatile int*)&g_pub[b]) = winc | FLAGB;
    }
    __syncwarp(0xffffffffu);
    if (t < 32) {
        int sum = 0;
        for (int p = t; p < b; p += 32) {
            int pv;
            do { pv = *((volatile int*)&g_pub[p]); } while (!(pv & FLAGB));
            sum += pv & ~FLAGB;
        }
        #pragma unroll
        for (int o = 16; o > 0; o >>= 1)
            sum += __shfl_down_sync(0xffffffffu, sum, o);
        if (t == 0) s_prefix = sum;
    }
    __syncthreads();
    if (idx < N_NODES) {
        int off = s_prefix + ws[t >> 5] + (inc - v);
        g_off[idx] = off;
        g_cur[idx] = off;
        float d = rsqrtf((float)(v + 1));
        g_dis[idx] = d;
        const float* xr = x + (size_t)idx * IN_C;
        float* xo = g_xs + (size_t)idx * 12;
        #pragma unroll
        for (int c = 0; c < IN_C; c++) xo[c] = __ldg(&xr[c]) * d;
        xo[10] = 0.0f; xo[11] = 0.0f;
    }
    if (idx == 0) g_off[N_NODES] = E_EDGES;
}

// CSR fill (src only) + reset cnt/pub for the next call
__global__ void k_fill(const int* __restrict__ ei) {
    int e = blockIdx.x * blockDim.x + threadIdx.x;
    if (e < 256) g_pub[e] = 0;
    if (e < N_NODES) g_cnt[e] = 0;
    if (e >= E_EDGES) return;
    int row = __ldg(&ei[e]);
    int col = __ldg(&ei[E_EDGES + e]);
    int pos = atomicAdd(&g_cur[col], 1);
    g_src[pos] = row;
}

// Fused layer 1, 64 nodes per 384-thread block (grid 782).
#define F1NPB 64
__global__ __launch_bounds__(384) void k_fused1(
        const float* __restrict__ W1, const float* __restrict__ b1) {
    __shared__ float sagg[F1NPB * 12];
    __shared__ __align__(16) float sW1[IN_C * HID];
    __shared__ float sb1[HID];
    int tid = threadIdx.x;
    int base = blockIdx.x * F1NPB;

    for (int t = tid; t < IN_C * HID; t += 384) sW1[t] = __ldg(&W1[t]);
    if (tid < HID) sb1[tid] = __ldg(&b1[tid]);

    // ---- phase A: aggregation (12 ch x 32 node-slots, 2 passes) ----
    int c    = tid % 12;
    int half = tid / 12;
    #pragma unroll
    for (int pass = 0; pass < 2; pass++) {
        int nd = pass * 32 + half;
        int n = base + nd;
        float acc = 0.0f;
        if (n < N_NODES) {
            acc = g_xs[(size_t)n * 12 + c];
            int s = g_off[n], e = g_off[n + 1];
            int last = e - 1;
            for (int i = s; i < e; i += 4) {
                #pragma unroll
                for (int k = 0; k < 4; k++) {
                    int ik = min(i + k, last);
                    int sk = __ldg(&g_src[ik]);
                    float vv = __ldg(&g_xs[(size_t)sk * 12 + c]);
                    acc += (i + k <= last) ? vv : 0.0f;
                }
            }
            acc *= g_dis[n];
        }
        sagg[nd * 12 + c] = acc;
    }
    __syncthreads();

    // ---- phase B: projection (8 j x 2 nodes / thread), relu*dis ----
    int tx = tid % 12, ty = tid / 12;
    int j8 = tx * 8;
    float4 a0[2], a1[2];
    {
        float4 b0 = *(const float4*)&sb1[j8];
        float4 b1v = *(const float4*)&sb1[j8 + 4];
        #pragma unroll
        for (int k = 0; k < 2; k++) { a0[k] = b0; a1[k] = b1v; }
    }
    #pragma unroll
    for (int cc = 0; cc < IN_C; cc++) {
        float4 w0 = *(const float4*)&sW1[cc * HID + j8];
        float4 w1 = *(const float4*)&sW1[cc * HID + j8 + 4];
        #pragma unroll
        for (int k = 0; k < 2; k++) {
            float a = sagg[(ty * 2 + k) * 12 + cc];
            a0[k].x += a * w0.x; a0[k].y += a * w0.y;
            a0[k].z += a * w0.z; a0[k].w += a * w0.w;
            a1[k].x += a * w1.x; a1[k].y += a * w1.y;
            a1[k].z += a * w1.z; a1[k].w += a * w1.w;
        }
    }
    #pragma unroll
    for (int k = 0; k < 2; k++) {
        int n = base + ty * 2 + k;
        if (n >= N_NODES) continue;
        float d = g_dis[n];
        float4 r0, r1;
        r0.x = fmaxf(a0[k].x, 0.f) * d; r0.y = fmaxf(a0[k].y, 0.f) * d;
        r0.z = fmaxf(a0[k].z, 0.f) * d; r0.w = fmaxf(a0[k].w, 0.f) * d;
        r1.x = fmaxf(a1[k].x, 0.f) * d; r1.y = fmaxf(a1[k].y, 0.f) * d;
        r1.z = fmaxf(a1[k].z, 0.f) * d; r1.w = fmaxf(a1[k].w, 0.f) * d;
        *(float4*)&g_hs[(size_t)n * HID + j8] = r0;
        *(float4*)&g_hs[(size_t)n * HID + j8 + 4] = r1;
    }
}

// agg_h: float4-vectorized gather-sum. block (24,16) = 384 thr, 16 nodes/blk.
// Thread owns 4 channels; one warp-gather covers a whole 384B row.
__global__ __launch_bounds__(384) void k_aggh_csr() {
    int n = blockIdx.x * 16 + threadIdx.y;
    if (n >= N_NODES) return;
    int tx = threadIdx.x;                   // 0..23 -> channels tx*4..tx*4+3
    const float4* hs4 = (const float4*)g_hs;
    float4 acc = __ldg(&hs4[(size_t)n * 24 + tx]);
    int s = g_off[n], e = g_off[n + 1];
    int last = e - 1;
    for (int i = s; i < e; i += 4) {
        #pragma unroll
        for (int k = 0; k < 4; k++) {
            int ik = min(i + k, last);
            int sk = __ldg(&g_src[ik]);
            float4 v = __ldg(&hs4[(size_t)sk * 24 + tx]);
            bool ok = (i + k <= last);
            acc.x += ok ? v.x : 0.0f;
            acc.y += ok ? v.y : 0.0f;
            acc.z += ok ? v.z : 0.0f;
            acc.w += ok ? v.w : 0.0f;
        }
    }
    float d = g_dis[n];
    acc.x *= d; acc.y *= d; acc.z *= d; acc.w *= d;
    ((float4*)g_aggh)[(size_t)n * 24 + tx] = acc;
}

// Output GEMM: block (12,8) = 96 thr; thread = 8 j-cols x 8 nodes; 64 nodes/blk.
#define ONPB 64
__global__ void k_out(const float* __restrict__ Wmu,
                      const float* __restrict__ bmu,
                      const float* __restrict__ Wls,
                      const float* __restrict__ bls,
                      float* __restrict__ out) {
    __shared__ __align__(16) float sW[24 * HID];
    __shared__ float sh[ONPB * 97];
    __shared__ float sb[HID];
    int tx = threadIdx.x, ty = threadIdx.y;
    int tid = ty * 12 + tx;
    int base = blockIdx.x * ONPB;

    if (tid < HID)
        sb[tid] = (tid < OUT_C) ? __ldg(&bmu[tid]) : __ldg(&bls[tid - OUT_C]);
    for (int t = tid; t < ONPB * 24; t += 96) {
        int nd = t / 24, c4 = (t - nd * 24) * 4;
        int n = base + nd;
        float4 v = (n < N_NODES) ? __ldg((const float4*)&g_aggh[(size_t)n * HID + c4])
                                 : make_float4(0.f, 0.f, 0.f, 0.f);
        float* dst = &sh[nd * 97 + c4];
        dst[0] = v.x; dst[1] = v.y; dst[2] = v.z; dst[3] = v.w;
    }

    int j8 = tx * 8;
    float4 acc0[8], acc1[8];
    {
        __syncthreads();
        float4 b0 = *(const float4*)&sb[j8];
        float4 b1v = *(const float4*)&sb[j8 + 4];
        #pragma unroll
        for (int k = 0; k < 8; k++) { acc0[k] = b0; acc1[k] = b1v; }
    }

    #pragma unroll
    for (int cb = 0; cb < 4; cb++) {
        for (int t = tid; t < 24 * 24; t += 96) {
            int r = t / 24, q4 = (t - r * 24) * 4;
            int c = cb * 24 + r;
            float4 w;
            if (q4 < OUT_C) {
                w = __ldg((const float4*)&Wmu[c * OUT_C + q4]);
            } else {
                w = __ldg((const float4*)&Wls[c * OUT_C + (q4 - OUT_C)]);
            }
            *(float4*)&sW[r * HID + q4] = w;
        }
        __syncthreads();
        #pragma unroll 4
        for (int c = 0; c < 24; c++) {
            float4 w0 = *(const float4*)&sW[c * HID + j8];
            float4 w1 = *(const float4*)&sW[c * HID + j8 + 4];
            #pragma unroll
            for (int k = 0; k < 8; k++) {
                float a = sh[(ty * 8 + k) * 97 + cb * 24 + c];
                acc0[k].x += a * w0.x; acc0[k].y += a * w0.y;
                acc0[k].z += a * w0.z; acc0[k].w += a * w0.w;
                acc1[k].x += a * w1.x; acc1[k].y += a * w1.y;
                acc1[k].z += a * w1.z; acc1[k].w += a * w1.w;
            }
        }
        __syncthreads();
    }

    #pragma unroll
    for (int k = 0; k < 8; k++) {
        int n = base + ty * 8 + k;
        if (n >= N_NODES) continue;
        if (j8 < OUT_C) {
            *(float4*)&out[(size_t)n * OUT_C + j8] = acc0[k];
            *(float4*)&out[(size_t)n * OUT_C + j8 + 4] = acc1[k];
        } else {
            size_t o = (size_t)N_NODES * OUT_C + (size_t)n * OUT_C + (j8 - OUT_C);
            *(float4*)&out[o] = acc0[k];
            *(float4*)&out[o + 4] = acc1[k];
        }
    }
}

extern "C" void kernel_launch(void* const* d_in, const int* in_sizes, int n_in,
                              void* d_out, int out_size) {
    const float* x   = (const float*)d_in[0];
    const int*   ei  = (const int*)d_in[1];
    const float* W1  = (const float*)d_in[2];
    const float* b1  = (const float*)d_in[3];
    const float* Wmu = (const float*)d_in[4];
    const float* bmu = (const float*)d_in[5];
    const float* Wls = (const float*)d_in[6];
    const float* bls = (const float*)d_in[7];
    float* out = (float*)d_out;

    k_count<<<(E_EDGES / 2 + 255) / 256, 256>>>(ei);
    k_scanfuse<<<SCAN_B, 256>>>(x);
    k_fill<<<(E_EDGES + 255) / 256, 256>>>(ei);
    k_fused1<<<(N_NODES + F1NPB - 1) / F1NPB, 384>>>(W1, b1);
    k_aggh_csr<<<(N_NODES + 15) / 16, dim3(24, 16)>>>();
    k_out<<<(N_NODES + ONPB - 1) / ONPB, dim3(12, 8)>>>(Wmu, bmu, Wls, bls, out);
}